// round 15
// baseline (speedup 1.0000x reference)
#include <cuda_runtime.h>
#include <cuda_bf16.h>
#include <cstdint>

#define MAX_NODES 50000
#define MAX_EDGES 1600000
#define KDIM 3703
#define KPAD 3712
#define BK32 32
#define KSPLIT 3
// per-stage SMEM: A fp32 128x36 (18432 B) + B 16x132 u32 (8448 B) + Abf 128x20 u32 (10240 B)
#define A_BYTES 18432
#define B_BYTES 8448
#define ABF_OFF (A_BYTES + B_BYTES)
#define STAGE_BYTES 37120

__device__ float g_h1[MAX_NODES * 128];
__device__ uint32_t g_h1bf[MAX_NODES * 64];
__device__ float g_agg1[MAX_NODES * 128];
__device__ uint32_t g_h2bf[MAX_NODES * 32];
__device__ float g_z2[MAX_NODES * 64];
__device__ float g_dinv[MAX_NODES];
__device__ uint32_t g_W1B[(KPAD / 2) * 128];  // W1 as bf16x2 k-pairs
__device__ float g_zeros[16];
__device__ int g_cnt[MAX_NODES];
__device__ int g_row[MAX_NODES];
__device__ int g_cursor[MAX_NODES];
__device__ int g_part[256];
__device__ int g_partscan[256];
__device__ int g_csr_src[MAX_EDGES];

// ---------------- helpers ---------------------------------------------------------
__device__ __forceinline__ void cp4(uint32_t dst, const void* src) {
    asm volatile("cp.async.ca.shared.global [%0], [%1], 4;"
                 :: "r"(dst), "l"(src) : "memory");
}
__device__ __forceinline__ void cp16(uint32_t dst, const void* src) {
    asm volatile("cp.async.cg.shared.global [%0], [%1], 16;"
                 :: "r"(dst), "l"(src) : "memory");
}
#define CP_COMMIT() asm volatile("cp.async.commit_group;" ::: "memory")
#define CP_WAIT(n)  asm volatile("cp.async.wait_group %0;" :: "n"(n) : "memory")
__device__ __forceinline__ uint32_t smem_u32(const void* p) {
    uint32_t a;
    asm("{ .reg .u64 t; cvta.to.shared.u64 t, %1; cvt.u32.u64 %0, t; }"
        : "=r"(a) : "l"(p));
    return a;
}
__device__ __forceinline__ uint32_t pack_bf2(float lo, float hi) {
    uint32_t r;
    asm("cvt.rn.bf16x2.f32 %0, %1, %2;" : "=r"(r) : "f"(hi), "f"(lo));
    return r;
}
__device__ __forceinline__ float2 unpack_bf2(uint32_t u) {
    __nv_bfloat162 b = *reinterpret_cast<__nv_bfloat162*>(&u);
    return __bfloat1622float2(b);
}

// ---------------- W1 -> bf16x2 k-pairs [k/2][n], zero padded -----------------------
__global__ void k_w1b(const float* __restrict__ W1) {
    int idx = blockIdx.x * blockDim.x + threadIdx.x;
    if (idx >= (KPAD / 2) * 128) return;
    int kp = idx >> 7, n = idx & 127;
    int k = kp * 2;
    float lo = (k < KDIM)     ? W1[(long long)k * 128 + n]       : 0.0f;
    float hi = (k + 1 < KDIM) ? W1[(long long)(k + 1) * 128 + n] : 0.0f;
    g_W1B[idx] = pack_bf2(lo, hi);
}

// ---------------- CSR build ---------------------------------------------------------
__global__ void k_hist(const int* __restrict__ ei, int E) {
    int e = blockIdx.x * blockDim.x + threadIdx.x;
    if (e < E) atomicAdd(&g_cnt[ei[E + e]], 1);
}
__global__ void k_scan_part(int n) {
    __shared__ int sh[256];
    int i = blockIdx.x * 256 + threadIdx.x;
    int v = (i < n) ? g_cnt[i] : 0;
    sh[threadIdx.x] = v;
    __syncthreads();
    for (int off = 128; off > 0; off >>= 1) {
        if (threadIdx.x < off) sh[threadIdx.x] += sh[threadIdx.x + off];
        __syncthreads();
    }
    if (threadIdx.x == 0) g_part[blockIdx.x] = sh[0];
}
__global__ void k_scan_top(int nblk) {
    __shared__ int sh[256];
    int tid = threadIdx.x;
    int v = (tid < nblk) ? g_part[tid] : 0;
    sh[tid] = v;
    __syncthreads();
    for (int off = 1; off < 256; off <<= 1) {
        int t = (tid >= off) ? sh[tid - off] : 0;
        __syncthreads();
        sh[tid] += t;
        __syncthreads();
    }
    g_partscan[tid] = sh[tid] - v;
}
__global__ void k_scan_final(int n) {
    __shared__ int sh[256];
    int i = blockIdx.x * 256 + threadIdx.x;
    int tid = threadIdx.x;
    int v = (i < n) ? g_cnt[i] : 0;
    sh[tid] = v;
    __syncthreads();
    for (int off = 1; off < 256; off <<= 1) {
        int t = (tid >= off) ? sh[tid - off] : 0;
        __syncthreads();
        sh[tid] += t;
        __syncthreads();
    }
    if (i < n) {
        int rs = sh[tid] - v + g_partscan[blockIdx.x];
        g_row[i] = rs;
        g_cursor[i] = rs;
        g_dinv[i] = rsqrtf((float)(v + 1));
    }
}
__global__ void k_fill(const int* __restrict__ ei, int E) {
    int e = blockIdx.x * blockDim.x + threadIdx.x;
    if (e >= E) return;
    int s = ei[e], d = ei[E + e];
    int slot = atomicAdd(&g_cursor[d], 1);
    g_csr_src[slot] = s;
}

// ---------------- GEMM1 split-K=3 (39/39/38 x BK32) bf16 m16n8k16 -------------------
// A loaded fp32 (aligned 144B superset rows, skew off=((mg*3+k0)&3)), then
// converted ONCE per stage to packed bf16x2 tile Abf[128][20] (pad 20 ->
// conflict-free (20*grp+tg)%32 fragment banks). Frags: aligned 32-bit LDS.
__global__ __launch_bounds__(256, 2)
void k_gemm1_mma(const float* __restrict__ A, int M) {
    extern __shared__ char dyn[];
    const int tid = threadIdx.x;
    const int wid = tid >> 5;
    const int lane = tid & 31;
    const int grp = lane >> 2, tg = lane & 3;
    const int warp_m = wid >> 2, warp_n = wid & 3;   // 2x4 warps: 64-row x 32-col
    const int m0 = blockIdx.x * 128;
    const int y = blockIdx.y;
    const int kb_ch = (y == 0) ? 0 : (y == 1 ? 39 : 78);
    const int nsteps = (y == 2) ? 38 : 39;

    const uint32_t smem0 = smem_u32(dyn);

    float acc[4][4][4];
#pragma unroll
    for (int i = 0; i < 4; i++)
#pragma unroll
        for (int j = 0; j < 4; j++)
#pragma unroll
            for (int v = 0; v < 4; v++) acc[i][j][v] = 0.0f;

    auto load_stage = [&](int c, int s) {
        const int k0 = (kb_ch + c) * BK32;
        const uint32_t sA = smem0 + s * STAGE_BYTES;
        const uint32_t sB = sA + A_BYTES;
        if (k0 + 36 <= KDIM) {
#pragma unroll
            for (int i = 0; i < 5; i++) {
                int idx = i * 256 + tid;
                if (idx < 1152) {
                    int row = idx / 9, part = idx - row * 9;
                    int mg = m0 + row;
                    const float* src;
                    if (mg < M) {
                        long long g = (long long)mg * KDIM + k0;
                        src = A + (g & ~3LL) + part * 4;
                    } else {
                        src = g_zeros;
                    }
                    cp16(sA + (uint32_t)((row * 36 + part * 4) * 4), src);
                }
            }
        } else {
#pragma unroll
            for (int i = 0; i < 16; i++) {
                int idx = i * 256 + tid;
                int row = idx >> 5, kk = idx & 31;
                int mg = m0 + row, k = k0 + kk;
                int off = (mg * 3 + k0) & 3;
                const float* src = (mg < M && k < KDIM)
                                 ? A + (long long)mg * KDIM + k : g_zeros;
                cp4(sA + (uint32_t)((row * 36 + off + kk) * 4), src);
            }
        }
#pragma unroll
        for (int i = 0; i < 2; i++) {
            int idx = i * 256 + tid;
            int kp = idx >> 5, n4 = (idx & 31) * 4;
            cp16(sB + (uint32_t)((kp * 132 + n4) * 4),
                 g_W1B + (long long)(k0 / 2 + kp) * 128 + n4);
        }
        CP_COMMIT();
    };

    load_stage(0, 0);
    for (int c = 0; c < nsteps; c++) {
        const int s = c & 1;
        if (c + 1 < nsteps) { load_stage(c + 1, s ^ 1); CP_WAIT(1); }
        else                { CP_WAIT(0); }
        __syncthreads();
        const int k0 = (kb_ch + c) * BK32;
        const float*    Asb  = (const float*)(dyn + s * STAGE_BYTES);
        const uint32_t* Bsb  = (const uint32_t*)(dyn + s * STAGE_BYTES + A_BYTES);
        uint32_t*       AbfW = (uint32_t*)(dyn + s * STAGE_BYTES + ABF_OFF);

        // cooperative fp32 -> bf16x2 conversion: 128 rows x 16 words
        {
            int row = tid >> 1, h8 = tid & 1;
            int off = ((m0 + row) * 3 + k0) & 3;
            const float* srcp = Asb + row * 36 + off + h8 * 16;
            uint32_t* dstp = AbfW + row * 20 + h8 * 8;
#pragma unroll
            for (int j = 0; j < 8; j++)
                dstp[j] = pack_bf2(srcp[2 * j], srcp[2 * j + 1]);
        }
        __syncthreads();

#pragma unroll
        for (int half = 0; half < 2; half++) {
            uint32_t bf[4][2];
#pragma unroll
            for (int nt = 0; nt < 4; nt++) {
                int n = warp_n * 32 + nt * 8 + grp;
                bf[nt][0] = Bsb[(half * 8 + tg) * 132 + n];
                bf[nt][1] = Bsb[(half * 8 + tg + 4) * 132 + n];
            }
#pragma unroll
            for (int mt = 0; mt < 4; mt++) {
                int r = warp_m * 64 + mt * 16 + grp;
                int r2 = r + 8;
                const uint32_t* R1 = AbfW + r * 20 + half * 8;
                const uint32_t* R2 = AbfW + r2 * 20 + half * 8;
                uint32_t a0 = R1[tg];
                uint32_t a1 = R2[tg];
                uint32_t a2 = R1[tg + 4];
                uint32_t a3 = R2[tg + 4];
#pragma unroll
                for (int nt = 0; nt < 4; nt++) {
                    asm volatile(
                        "mma.sync.aligned.m16n8k16.row.col.f32.bf16.bf16.f32 "
                        "{%0, %1, %2, %3}, {%4, %5, %6, %7}, {%8, %9}, "
                        "{%0, %1, %2, %3};"
                        : "+f"(acc[mt][nt][0]), "+f"(acc[mt][nt][1]),
                          "+f"(acc[mt][nt][2]), "+f"(acc[mt][nt][3])
                        : "r"(a0), "r"(a1), "r"(a2), "r"(a3),
                          "r"(bf[nt][0]), "r"(bf[nt][1]));
                }
            }
        }
        __syncthreads();
    }
#pragma unroll
    for (int mt = 0; mt < 4; mt++) {
        int r = m0 + warp_m * 64 + mt * 16 + grp;
#pragma unroll
        for (int nt = 0; nt < 4; nt++) {
            int col = warp_n * 32 + nt * 8 + tg * 2;
            if (r < M) {
                float* p = g_h1 + (long long)r * 128 + col;
                asm volatile("red.global.add.v2.f32 [%0], {%1, %2};"
                             :: "l"(p), "f"(acc[mt][nt][0]), "f"(acc[mt][nt][1])
                             : "memory");
            }
            if (r + 8 < M) {
                float* p = g_h1 + (long long)(r + 8) * 128 + col;
                asm volatile("red.global.add.v2.f32 [%0], {%1, %2};"
                             :: "l"(p), "f"(acc[mt][nt][2]), "f"(acc[mt][nt][3])
                             : "memory");
            }
        }
    }
}

// ---------------- h1 -> packed bf16 -------------------------------------------------
__global__ void k_h1bf(int n) {
    int i = blockIdx.x * blockDim.x + threadIdx.x;
    if (i >= n * 64) return;
    float2 v = ((const float2*)g_h1)[i];
    g_h1bf[i] = pack_bf2(v.x, v.y);
}

// ---------------- layer-1 gather (warp per node; bf16 neighbor rows) ----------------
__global__ void k_gather1(const float* __restrict__ b1, int n) {
    long long gid = (long long)blockIdx.x * blockDim.x + threadIdx.x;
    int i = (int)(gid >> 5);
    if (i >= n) return;
    int l = (int)gid & 31;
    float di = g_dinv[i];
    float4 h = *(const float4*)(g_h1 + (long long)i * 128 + l * 4);
    float4 acc = make_float4(h.x * di, h.y * di, h.z * di, h.w * di);
    int rs = g_row[i], re = rs + g_cnt[i];
    int j = rs;
    for (; j + 4 <= re; j += 4) {
        int s0 = g_csr_src[j], s1 = g_csr_src[j + 1];
        int s2 = g_csr_src[j + 2], s3 = g_csr_src[j + 3];
        float c0 = g_dinv[s0], c1 = g_dinv[s1], c2 = g_dinv[s2], c3 = g_dinv[s3];
        uint2 u0 = *(const uint2*)(g_h1bf + (long long)s0 * 64 + l * 2);
        uint2 u1 = *(const uint2*)(g_h1bf + (long long)s1 * 64 + l * 2);
        uint2 u2 = *(const uint2*)(g_h1bf + (long long)s2 * 64 + l * 2);
        uint2 u3 = *(const uint2*)(g_h1bf + (long long)s3 * 64 + l * 2);
        float2 a0 = unpack_bf2(u0.x), b0 = unpack_bf2(u0.y);
        float2 a1 = unpack_bf2(u1.x), b1v = unpack_bf2(u1.y);
        float2 a2 = unpack_bf2(u2.x), b2v = unpack_bf2(u2.y);
        float2 a3 = unpack_bf2(u3.x), b3v = unpack_bf2(u3.y);
        acc.x += c0 * a0.x + c1 * a1.x + c2 * a2.x + c3 * a3.x;
        acc.y += c0 * a0.y + c1 * a1.y + c2 * a2.y + c3 * a3.y;
        acc.z += c0 * b0.x + c1 * b1v.x + c2 * b2v.x + c3 * b3v.x;
        acc.w += c0 * b0.y + c1 * b1v.y + c2 * b2v.y + c3 * b3v.y;
    }
    for (; j < re; j++) {
        int s = g_csr_src[j];
        float cf = g_dinv[s];
        uint2 u = *(const uint2*)(g_h1bf + (long long)s * 64 + l * 2);
        float2 a = unpack_bf2(u.x), b = unpack_bf2(u.y);
        acc.x += cf * a.x; acc.y += cf * a.y;
        acc.z += cf * b.x; acc.w += cf * b.y;
    }
    float4 bb = *(const float4*)(b1 + l * 4);
    *(float4*)(g_agg1 + (long long)i * 128 + l * 4) =
        make_float4(acc.x * di + bb.x, acc.y * di + bb.y,
                    acc.z * di + bb.z, acc.w * di + bb.w);
}

// ---------------- GEMM2 (writes h2 as packed bf16) ------------------------------------
__global__ __launch_bounds__(256)
void k_gemm2(const float* __restrict__ W2, int M) {
    __shared__ float Ws[128 * 64];
    __shared__ float Zs[16 * 128];
    const int tid = threadIdx.x;
    const int n0 = blockIdx.x * 16;
#pragma unroll
    for (int i = 0; i < 8; i++)
        ((float4*)Ws)[i * 256 + tid] = ((const float4*)W2)[i * 256 + tid];
#pragma unroll
    for (int i = 0; i < 2; i++) {
        int f4 = i * 256 + tid;
        int node = n0 + (f4 >> 5);
        float4 v = make_float4(0.f, 0.f, 0.f, 0.f);
        if (node < M) v = ((const float4*)(g_agg1 + (long long)node * 128))[f4 & 31];
        v.x = fmaxf(v.x, 0.f); v.y = fmaxf(v.y, 0.f);
        v.z = fmaxf(v.z, 0.f); v.w = fmaxf(v.w, 0.f);
        ((float4*)Zs)[f4] = v;
    }
    __syncthreads();
    const int ny = tid / 16, nx = (tid % 16) * 4;
    float4 acc = make_float4(0.f, 0.f, 0.f, 0.f);
#pragma unroll
    for (int k = 0; k < 128; k++) {
        float a = Zs[ny * 128 + k];
        float4 w = *(const float4*)(&Ws[k * 64 + nx]);
        acc.x += a * w.x; acc.y += a * w.y;
        acc.z += a * w.z; acc.w += a * w.w;
    }
    int node = n0 + ny;
    if (node < M) {
        uint2 packed = make_uint2(pack_bf2(acc.x, acc.y), pack_bf2(acc.z, acc.w));
        *(uint2*)(g_h2bf + (long long)node * 32 + nx / 2) = packed;
    }
}

// ---------------- layer-2 gather (16 lanes per node; bf16 rows) ------------------------
__global__ void k_gather2(const float* __restrict__ b2, int n) {
    long long gid = (long long)blockIdx.x * blockDim.x + threadIdx.x;
    int i = (int)(gid >> 4);
    if (i >= n) return;
    int l = (int)gid & 15;
    float di = g_dinv[i];
    uint2 us = *(const uint2*)(g_h2bf + (long long)i * 32 + l * 2);
    float2 sa = unpack_bf2(us.x), sb = unpack_bf2(us.y);
    float4 acc = make_float4(sa.x * di, sa.y * di, sb.x * di, sb.y * di);
    int rs = g_row[i], re = rs + g_cnt[i];
    int j = rs;
    for (; j + 4 <= re; j += 4) {
        int s0 = g_csr_src[j], s1 = g_csr_src[j + 1];
        int s2 = g_csr_src[j + 2], s3 = g_csr_src[j + 3];
        float c0 = g_dinv[s0], c1 = g_dinv[s1], c2 = g_dinv[s2], c3 = g_dinv[s3];
        uint2 u0 = *(const uint2*)(g_h2bf + (long long)s0 * 32 + l * 2);
        uint2 u1 = *(const uint2*)(g_h2bf + (long long)s1 * 32 + l * 2);
        uint2 u2 = *(const uint2*)(g_h2bf + (long long)s2 * 32 + l * 2);
        uint2 u3 = *(const uint2*)(g_h2bf + (long long)s3 * 32 + l * 2);
        float2 a0 = unpack_bf2(u0.x), b0 = unpack_bf2(u0.y);
        float2 a1 = unpack_bf2(u1.x), b1v = unpack_bf2(u1.y);
        float2 a2 = unpack_bf2(u2.x), b2v = unpack_bf2(u2.y);
        float2 a3 = unpack_bf2(u3.x), b3v = unpack_bf2(u3.y);
        acc.x += c0 * a0.x + c1 * a1.x + c2 * a2.x + c3 * a3.x;
        acc.y += c0 * a0.y + c1 * a1.y + c2 * a2.y + c3 * a3.y;
        acc.z += c0 * b0.x + c1 * b1v.x + c2 * b2v.x + c3 * b3v.x;
        acc.w += c0 * b0.y + c1 * b1v.y + c2 * b2v.y + c3 * b3v.y;
    }
    for (; j < re; j++) {
        int s = g_csr_src[j];
        float cf = g_dinv[s];
        uint2 u = *(const uint2*)(g_h2bf + (long long)s * 32 + l * 2);
        float2 a = unpack_bf2(u.x), b = unpack_bf2(u.y);
        acc.x += cf * a.x; acc.y += cf * a.y;
        acc.z += cf * b.x; acc.w += cf * b.y;
    }
    float4 bb = *(const float4*)(b2 + l * 4);
    *(float4*)(g_z2 + (long long)i * 64 + l * 4) =
        make_float4(acc.x * di + bb.x, acc.y * di + bb.y,
                    acc.z * di + bb.z, acc.w * di + bb.w);
}

// ---------------- decoder (16 lanes per edge, float4) ----------------------------------
__global__ void k_decode(const int* __restrict__ eli, float* __restrict__ out,
                         int NL) {
    long long gid = (long long)blockIdx.x * blockDim.x + threadIdx.x;
    int e = (int)(gid >> 4);
    if (e >= NL) return;
    int l = (int)gid & 15;
    int a = eli[e], b = eli[NL + e];
    float4 va = *(const float4*)(g_z2 + (long long)a * 64 + l * 4);
    float4 vb = *(const float4*)(g_z2 + (long long)b * 64 + l * 4);
    float p = va.x * vb.x + va.y * vb.y + va.z * vb.z + va.w * vb.w;
#pragma unroll
    for (int off = 8; off > 0; off >>= 1)
        p += __shfl_xor_sync(0xFFFFFFFFu, p, off);
    if (l == 0) out[e] = p;
}

// ---------------- launch ---------------------------------------------------------------------
extern "C" void kernel_launch(void* const* d_in, const int* in_sizes, int n_in,
                              void* d_out, int out_size) {
    const float* x  = (const float*)d_in[0];
    const float* W1 = (const float*)d_in[1];
    const float* b1 = (const float*)d_in[2];
    const float* W2 = (const float*)d_in[3];
    const float* b2 = (const float*)d_in[4];
    const int* ei  = (const int*)d_in[5];
    const int* eli = (const int*)d_in[6];
    float* out = (float*)d_out;

    const int K  = in_sizes[1] / 128;
    const int Nn = in_sizes[0] / K;
    const int E  = in_sizes[5] / 2;
    const int NL = in_sizes[6] / 2;
    const int nblk = (Nn + 255) / 256;
    const int SMEM = 2 * STAGE_BYTES;   // 74240 B

    cudaFuncSetAttribute(k_gemm1_mma, cudaFuncAttributeMaxDynamicSharedMemorySize,
                         SMEM);

    // side stream + fork/join events
    cudaStream_t s2;
    cudaStreamCreateWithFlags(&s2, cudaStreamNonBlocking);
    cudaEvent_t evFork, evJoin, evMemH1;
    cudaEventCreateWithFlags(&evFork, cudaEventDisableTiming);
    cudaEventCreateWithFlags(&evJoin, cudaEventDisableTiming);
    cudaEventCreateWithFlags(&evMemH1, cudaEventDisableTiming);

    cudaEventRecord(evFork, 0);
    cudaStreamWaitEvent(s2, evFork, 0);

    // side branch: zero h1, then CSR build
    void* p = nullptr;
    cudaGetSymbolAddress(&p, g_h1);
    cudaMemsetAsync(p, 0, (size_t)Nn * 128 * sizeof(float), s2);
    cudaEventRecord(evMemH1, s2);
    void* pc = nullptr;
    cudaGetSymbolAddress(&pc, g_cnt);
    cudaMemsetAsync(pc, 0, (size_t)Nn * sizeof(int), s2);
    k_hist<<<(E + 255) / 256, 256, 0, s2>>>(ei, E);
    k_scan_part<<<nblk, 256, 0, s2>>>(Nn);
    k_scan_top<<<1, 256, 0, s2>>>(nblk);
    k_scan_final<<<nblk, 256, 0, s2>>>(Nn);
    k_fill<<<(E + 255) / 256, 256, 0, s2>>>(ei, E);
    cudaEventRecord(evJoin, s2);

    // main chain
    k_w1b<<<((KPAD / 2) * 128 + 255) / 256, 256>>>(W1);
    cudaStreamWaitEvent(0, evMemH1, 0);
    {
        dim3 grid((Nn + 127) / 128, KSPLIT);
        k_gemm1_mma<<<grid, 256, SMEM>>>(x, Nn);
    }
    k_h1bf<<<(Nn * 64 + 255) / 256, 256>>>(Nn);

    cudaStreamWaitEvent(0, evJoin, 0);

    { long long t = (long long)Nn * 32;
      k_gather1<<<(unsigned)((t + 255) / 256), 256>>>(b1, Nn); }

    k_gemm2<<<(Nn + 15) / 16, 256>>>(W2, Nn);
    { long long t = (long long)Nn * 16;
      k_gather2<<<(unsigned)((t + 255) / 256), 256>>>(b2, Nn); }

    { long long t = (long long)NL * 16;
      k_decode<<<(unsigned)((t + 255) / 256), 256>>>(eli, out, NL); }
}

// round 16
// speedup vs baseline: 1.0811x; 1.0811x over previous
#include <cuda_runtime.h>
#include <cuda_bf16.h>
#include <cstdint>

#define MAX_NODES 50000
#define MAX_EDGES 1600000
#define KDIM 3703
#define KPAD 3712
#define BK32 32
#define KSPLIT 3
// per-stage SMEM: A 128x36 fp32 (18432 B) + B 16x132 u32 (8448 B)
#define A_BYTES 18432
#define STAGE_BYTES 26880

__device__ float g_h1[MAX_NODES * 128];
__device__ uint32_t g_h1bf[MAX_NODES * 64];
__device__ float g_agg1[MAX_NODES * 128];
__device__ uint32_t g_h2bf[MAX_NODES * 32];
__device__ float g_z2[MAX_NODES * 64];
__device__ float g_dinv[MAX_NODES];
__device__ uint32_t g_W1B[(KPAD / 2) * 128];  // W1 as bf16x2 k-pairs
__device__ float g_zeros[16];
__device__ int g_cnt[MAX_NODES];
__device__ int g_row[MAX_NODES];
__device__ int g_cursor[MAX_NODES];
__device__ int g_part[256];
__device__ int g_partscan[256];
__device__ int g_csr_src[MAX_EDGES];

// ---------------- helpers ---------------------------------------------------------
__device__ __forceinline__ void cp4(uint32_t dst, const void* src) {
    asm volatile("cp.async.ca.shared.global [%0], [%1], 4;"
                 :: "r"(dst), "l"(src) : "memory");
}
__device__ __forceinline__ void cp16(uint32_t dst, const void* src) {
    asm volatile("cp.async.cg.shared.global [%0], [%1], 16;"
                 :: "r"(dst), "l"(src) : "memory");
}
#define CP_COMMIT() asm volatile("cp.async.commit_group;" ::: "memory")
#define CP_WAIT(n)  asm volatile("cp.async.wait_group %0;" :: "n"(n) : "memory")
__device__ __forceinline__ uint32_t smem_u32(const void* p) {
    uint32_t a;
    asm("{ .reg .u64 t; cvta.to.shared.u64 t, %1; cvt.u32.u64 %0, t; }"
        : "=r"(a) : "l"(p));
    return a;
}
__device__ __forceinline__ uint32_t pack_bf2(float lo, float hi) {
    uint32_t r;
    asm("cvt.rn.bf16x2.f32 %0, %1, %2;" : "=r"(r) : "f"(hi), "f"(lo));
    return r;
}
__device__ __forceinline__ float2 unpack_bf2(uint32_t u) {
    __nv_bfloat162 b = *reinterpret_cast<__nv_bfloat162*>(&u);
    return __bfloat1622float2(b);
}

// ---------------- W1 -> bf16x2 k-pairs [k/2][n], zero padded -----------------------
__global__ void k_w1b(const float* __restrict__ W1) {
    int idx = blockIdx.x * blockDim.x + threadIdx.x;
    if (idx >= (KPAD / 2) * 128) return;
    int kp = idx >> 7, n = idx & 127;
    int k = kp * 2;
    float lo = (k < KDIM)     ? W1[(long long)k * 128 + n]       : 0.0f;
    float hi = (k + 1 < KDIM) ? W1[(long long)(k + 1) * 128 + n] : 0.0f;
    g_W1B[idx] = pack_bf2(lo, hi);
}

// ---------------- CSR build ---------------------------------------------------------
__global__ void k_hist(const int* __restrict__ ei, int E) {
    int e = blockIdx.x * blockDim.x + threadIdx.x;
    if (e < E) atomicAdd(&g_cnt[ei[E + e]], 1);
}
__global__ void k_scan_part(int n) {
    __shared__ int sh[256];
    int i = blockIdx.x * 256 + threadIdx.x;
    int v = (i < n) ? g_cnt[i] : 0;
    sh[threadIdx.x] = v;
    __syncthreads();
    for (int off = 128; off > 0; off >>= 1) {
        if (threadIdx.x < off) sh[threadIdx.x] += sh[threadIdx.x + off];
        __syncthreads();
    }
    if (threadIdx.x == 0) g_part[blockIdx.x] = sh[0];
}
__global__ void k_scan_top(int nblk) {
    __shared__ int sh[256];
    int tid = threadIdx.x;
    int v = (tid < nblk) ? g_part[tid] : 0;
    sh[tid] = v;
    __syncthreads();
    for (int off = 1; off < 256; off <<= 1) {
        int t = (tid >= off) ? sh[tid - off] : 0;
        __syncthreads();
        sh[tid] += t;
        __syncthreads();
    }
    g_partscan[tid] = sh[tid] - v;
}
__global__ void k_scan_final(int n) {
    __shared__ int sh[256];
    int i = blockIdx.x * 256 + threadIdx.x;
    int tid = threadIdx.x;
    int v = (i < n) ? g_cnt[i] : 0;
    sh[tid] = v;
    __syncthreads();
    for (int off = 1; off < 256; off <<= 1) {
        int t = (tid >= off) ? sh[tid - off] : 0;
        __syncthreads();
        sh[tid] += t;
        __syncthreads();
    }
    if (i < n) {
        int rs = sh[tid] - v + g_partscan[blockIdx.x];
        g_row[i] = rs;
        g_cursor[i] = rs;
        g_dinv[i] = rsqrtf((float)(v + 1));
    }
}
__global__ void k_fill(const int* __restrict__ ei, int E) {
    int e = blockIdx.x * blockDim.x + threadIdx.x;
    if (e >= E) return;
    int s = ei[e], d = ei[E + e];
    int slot = atomicAdd(&g_cursor[d], 1);
    g_csr_src[slot] = s;
}

// ---------------- GEMM1 split-K=3 (39/39/38 x BK32) bf16 m16n8k16 -------------------
// A SMEM row = 36 fp32 (aligned 144B superset of the 32-float window); per-row
// skew off = ((mg*3 + k0) & 3). Garbage at k>=KDIM cancelled by zero-padded B.
__global__ __launch_bounds__(256, 2)
void k_gemm1_mma(const float* __restrict__ A, int M) {
    extern __shared__ char dyn[];
    const int tid = threadIdx.x;
    const int wid = tid >> 5;
    const int lane = tid & 31;
    const int grp = lane >> 2, tg = lane & 3;
    const int warp_m = wid >> 2, warp_n = wid & 3;   // 2x4 warps: 64-row x 32-col
    const int m0 = blockIdx.x * 128;
    const int y = blockIdx.y;
    const int kb_ch = (y == 0) ? 0 : (y == 1 ? 39 : 78);
    const int nsteps = (y == 2) ? 38 : 39;

    const uint32_t smem0 = smem_u32(dyn);

    float acc[4][4][4];
#pragma unroll
    for (int i = 0; i < 4; i++)
#pragma unroll
        for (int j = 0; j < 4; j++)
#pragma unroll
            for (int v = 0; v < 4; v++) acc[i][j][v] = 0.0f;

    auto load_stage = [&](int c, int s) {
        const int k0 = (kb_ch + c) * BK32;
        const uint32_t sA = smem0 + s * STAGE_BYTES;
        const uint32_t sB = sA + A_BYTES;
        if (k0 + 36 <= KDIM) {
#pragma unroll
            for (int i = 0; i < 5; i++) {
                int idx = i * 256 + tid;
                if (idx < 1152) {
                    int row = idx / 9, part = idx - row * 9;
                    int mg = m0 + row;
                    const float* src;
                    if (mg < M) {
                        long long g = (long long)mg * KDIM + k0;
                        src = A + (g & ~3LL) + part * 4;
                    } else {
                        src = g_zeros;
                    }
                    cp16(sA + (uint32_t)((row * 36 + part * 4) * 4), src);
                }
            }
        } else {
#pragma unroll
            for (int i = 0; i < 16; i++) {
                int idx = i * 256 + tid;
                int row = idx >> 5, kk = idx & 31;
                int mg = m0 + row, k = k0 + kk;
                int off = (mg * 3 + k0) & 3;
                const float* src = (mg < M && k < KDIM)
                                 ? A + (long long)mg * KDIM + k : g_zeros;
                cp4(sA + (uint32_t)((row * 36 + off + kk) * 4), src);
            }
        }
#pragma unroll
        for (int i = 0; i < 2; i++) {
            int idx = i * 256 + tid;
            int kp = idx >> 5, n4 = (idx & 31) * 4;
            cp16(sB + (uint32_t)((kp * 132 + n4) * 4),
                 g_W1B + (long long)(k0 / 2 + kp) * 128 + n4);
        }
        CP_COMMIT();
    };

    load_stage(0, 0);
    for (int c = 0; c < nsteps; c++) {
        const int s = c & 1;
        if (c + 1 < nsteps) { load_stage(c + 1, s ^ 1); CP_WAIT(1); }
        else                { CP_WAIT(0); }
        __syncthreads();
        const int k0 = (kb_ch + c) * BK32;
        const float*    Asb = (const float*)(dyn + s * STAGE_BYTES);
        const uint32_t* Bsb = (const uint32_t*)(dyn + s * STAGE_BYTES + A_BYTES);

#pragma unroll
        for (int half = 0; half < 2; half++) {
            const int kk = half * 16;
            uint32_t bf[4][2];
#pragma unroll
            for (int nt = 0; nt < 4; nt++) {
                int n = warp_n * 32 + nt * 8 + grp;
                bf[nt][0] = Bsb[(half * 8 + tg) * 132 + n];
                bf[nt][1] = Bsb[(half * 8 + tg + 4) * 132 + n];
            }
#pragma unroll
            for (int mt = 0; mt < 4; mt++) {
                int r = warp_m * 64 + mt * 16 + grp;
                int r2 = r + 8;
                int off1 = ((m0 + r) * 3 + k0) & 3;
                int off2 = ((m0 + r2) * 3 + k0) & 3;
                const float* A1 = Asb + r * 36 + off1 + kk;
                const float* A2 = Asb + r2 * 36 + off2 + kk;
                uint32_t a0 = pack_bf2(A1[2 * tg],     A1[2 * tg + 1]);
                uint32_t a1 = pack_bf2(A2[2 * tg],     A2[2 * tg + 1]);
                uint32_t a2 = pack_bf2(A1[2 * tg + 8], A1[2 * tg + 9]);
                uint32_t a3 = pack_bf2(A2[2 * tg + 8], A2[2 * tg + 9]);
#pragma unroll
                for (int nt = 0; nt < 4; nt++) {
                    asm volatile(
                        "mma.sync.aligned.m16n8k16.row.col.f32.bf16.bf16.f32 "
                        "{%0, %1, %2, %3}, {%4, %5, %6, %7}, {%8, %9}, "
                        "{%0, %1, %2, %3};"
                        : "+f"(acc[mt][nt][0]), "+f"(acc[mt][nt][1]),
                          "+f"(acc[mt][nt][2]), "+f"(acc[mt][nt][3])
                        : "r"(a0), "r"(a1), "r"(a2), "r"(a3),
                          "r"(bf[nt][0]), "r"(bf[nt][1]));
                }
            }
        }
        __syncthreads();
    }
#pragma unroll
    for (int mt = 0; mt < 4; mt++) {
        int r = m0 + warp_m * 64 + mt * 16 + grp;
#pragma unroll
        for (int nt = 0; nt < 4; nt++) {
            int col = warp_n * 32 + nt * 8 + tg * 2;
            if (r < M) {
                float* p = g_h1 + (long long)r * 128 + col;
                asm volatile("red.global.add.v2.f32 [%0], {%1, %2};"
                             :: "l"(p), "f"(acc[mt][nt][0]), "f"(acc[mt][nt][1])
                             : "memory");
            }
            if (r + 8 < M) {
                float* p = g_h1 + (long long)(r + 8) * 128 + col;
                asm volatile("red.global.add.v2.f32 [%0], {%1, %2};"
                             :: "l"(p), "f"(acc[mt][nt][2]), "f"(acc[mt][nt][3])
                             : "memory");
            }
        }
    }
}

// ---------------- h1 -> packed bf16 -------------------------------------------------
__global__ void k_h1bf(int n) {
    int i = blockIdx.x * blockDim.x + threadIdx.x;
    if (i >= n * 64) return;
    float2 v = ((const float2*)g_h1)[i];
    g_h1bf[i] = pack_bf2(v.x, v.y);
}

// ---------------- layer-1 gather (warp per node; bf16 rows; 8-edge unroll) ----------
__global__ void k_gather1(const float* __restrict__ b1, int n) {
    long long gid = (long long)blockIdx.x * blockDim.x + threadIdx.x;
    int i = (int)(gid >> 5);
    if (i >= n) return;
    int l = (int)gid & 31;
    float di = g_dinv[i];
    float4 h = *(const float4*)(g_h1 + (long long)i * 128 + l * 4);
    float4 acc = make_float4(h.x * di, h.y * di, h.z * di, h.w * di);
    int rs = g_row[i], re = rs + g_cnt[i];
    int j = rs;
    for (; j + 8 <= re; j += 8) {
        int sidx[8];
#pragma unroll
        for (int q = 0; q < 8; q++) sidx[q] = g_csr_src[j + q];
        float cf[8];
        uint2 u[8];
#pragma unroll
        for (int q = 0; q < 8; q++) {
            cf[q] = g_dinv[sidx[q]];
            u[q] = *(const uint2*)(g_h1bf + (long long)sidx[q] * 64 + l * 2);
        }
#pragma unroll
        for (int q = 0; q < 8; q++) {
            float2 a = unpack_bf2(u[q].x), b = unpack_bf2(u[q].y);
            acc.x += cf[q] * a.x; acc.y += cf[q] * a.y;
            acc.z += cf[q] * b.x; acc.w += cf[q] * b.y;
        }
    }
    for (; j < re; j++) {
        int s = g_csr_src[j];
        float cf = g_dinv[s];
        uint2 u = *(const uint2*)(g_h1bf + (long long)s * 64 + l * 2);
        float2 a = unpack_bf2(u.x), b = unpack_bf2(u.y);
        acc.x += cf * a.x; acc.y += cf * a.y;
        acc.z += cf * b.x; acc.w += cf * b.y;
    }
    float4 bb = *(const float4*)(b1 + l * 4);
    *(float4*)(g_agg1 + (long long)i * 128 + l * 4) =
        make_float4(acc.x * di + bb.x, acc.y * di + bb.y,
                    acc.z * di + bb.z, acc.w * di + bb.w);
}

// ---------------- GEMM2 (writes h2 as packed bf16) ------------------------------------
__global__ __launch_bounds__(256)
void k_gemm2(const float* __restrict__ W2, int M) {
    __shared__ float Ws[128 * 64];
    __shared__ float Zs[16 * 128];
    const int tid = threadIdx.x;
    const int n0 = blockIdx.x * 16;
#pragma unroll
    for (int i = 0; i < 8; i++)
        ((float4*)Ws)[i * 256 + tid] = ((const float4*)W2)[i * 256 + tid];
#pragma unroll
    for (int i = 0; i < 2; i++) {
        int f4 = i * 256 + tid;
        int node = n0 + (f4 >> 5);
        float4 v = make_float4(0.f, 0.f, 0.f, 0.f);
        if (node < M) v = ((const float4*)(g_agg1 + (long long)node * 128))[f4 & 31];
        v.x = fmaxf(v.x, 0.f); v.y = fmaxf(v.y, 0.f);
        v.z = fmaxf(v.z, 0.f); v.w = fmaxf(v.w, 0.f);
        ((float4*)Zs)[f4] = v;
    }
    __syncthreads();
    const int ny = tid / 16, nx = (tid % 16) * 4;
    float4 acc = make_float4(0.f, 0.f, 0.f, 0.f);
#pragma unroll
    for (int k = 0; k < 128; k++) {
        float a = Zs[ny * 128 + k];
        float4 w = *(const float4*)(&Ws[k * 64 + nx]);
        acc.x += a * w.x; acc.y += a * w.y;
        acc.z += a * w.z; acc.w += a * w.w;
    }
    int node = n0 + ny;
    if (node < M) {
        uint2 packed = make_uint2(pack_bf2(acc.x, acc.y), pack_bf2(acc.z, acc.w));
        *(uint2*)(g_h2bf + (long long)node * 32 + nx / 2) = packed;
    }
}

// ---------------- layer-2 gather (16 lanes per node; bf16 rows; 8-edge unroll) --------
__global__ void k_gather2(const float* __restrict__ b2, int n) {
    long long gid = (long long)blockIdx.x * blockDim.x + threadIdx.x;
    int i = (int)(gid >> 4);
    if (i >= n) return;
    int l = (int)gid & 15;
    float di = g_dinv[i];
    uint2 us = *(const uint2*)(g_h2bf + (long long)i * 32 + l * 2);
    float2 sa = unpack_bf2(us.x), sb = unpack_bf2(us.y);
    float4 acc = make_float4(sa.x * di, sa.y * di, sb.x * di, sb.y * di);
    int rs = g_row[i], re = rs + g_cnt[i];
    int j = rs;
    for (; j + 8 <= re; j += 8) {
        int sidx[8];
#pragma unroll
        for (int q = 0; q < 8; q++) sidx[q] = g_csr_src[j + q];
        float cf[8];
        uint2 u[8];
#pragma unroll
        for (int q = 0; q < 8; q++) {
            cf[q] = g_dinv[sidx[q]];
            u[q] = *(const uint2*)(g_h2bf + (long long)sidx[q] * 32 + l * 2);
        }
#pragma unroll
        for (int q = 0; q < 8; q++) {
            float2 a = unpack_bf2(u[q].x), b = unpack_bf2(u[q].y);
            acc.x += cf[q] * a.x; acc.y += cf[q] * a.y;
            acc.z += cf[q] * b.x; acc.w += cf[q] * b.y;
        }
    }
    for (; j < re; j++) {
        int s = g_csr_src[j];
        float cf = g_dinv[s];
        uint2 u = *(const uint2*)(g_h2bf + (long long)s * 32 + l * 2);
        float2 a = unpack_bf2(u.x), b = unpack_bf2(u.y);
        acc.x += cf * a.x; acc.y += cf * a.y;
        acc.z += cf * b.x; acc.w += cf * b.y;
    }
    float4 bb = *(const float4*)(b2 + l * 4);
    *(float4*)(g_z2 + (long long)i * 64 + l * 4) =
        make_float4(acc.x * di + bb.x, acc.y * di + bb.y,
                    acc.z * di + bb.z, acc.w * di + bb.w);
}

// ---------------- decoder (16 lanes per edge, float4) ----------------------------------
__global__ void k_decode(const int* __restrict__ eli, float* __restrict__ out,
                         int NL) {
    long long gid = (long long)blockIdx.x * blockDim.x + threadIdx.x;
    int e = (int)(gid >> 4);
    if (e >= NL) return;
    int l = (int)gid & 15;
    int a = eli[e], b = eli[NL + e];
    float4 va = *(const float4*)(g_z2 + (long long)a * 64 + l * 4);
    float4 vb = *(const float4*)(g_z2 + (long long)b * 64 + l * 4);
    float p = va.x * vb.x + va.y * vb.y + va.z * vb.z + va.w * vb.w;
#pragma unroll
    for (int off = 8; off > 0; off >>= 1)
        p += __shfl_xor_sync(0xFFFFFFFFu, p, off);
    if (l == 0) out[e] = p;
}

// ---------------- launch ---------------------------------------------------------------------
extern "C" void kernel_launch(void* const* d_in, const int* in_sizes, int n_in,
                              void* d_out, int out_size) {
    const float* x  = (const float*)d_in[0];
    const float* W1 = (const float*)d_in[1];
    const float* b1 = (const float*)d_in[2];
    const float* W2 = (const float*)d_in[3];
    const float* b2 = (const float*)d_in[4];
    const int* ei  = (const int*)d_in[5];
    const int* eli = (const int*)d_in[6];
    float* out = (float*)d_out;

    const int K  = in_sizes[1] / 128;
    const int Nn = in_sizes[0] / K;
    const int E  = in_sizes[5] / 2;
    const int NL = in_sizes[6] / 2;
    const int nblk = (Nn + 255) / 256;
    const int SMEM = 2 * STAGE_BYTES;   // 53760 B

    cudaFuncSetAttribute(k_gemm1_mma, cudaFuncAttributeMaxDynamicSharedMemorySize,
                         SMEM);

    // side stream + fork/join events
    cudaStream_t s2;
    cudaStreamCreateWithFlags(&s2, cudaStreamNonBlocking);
    cudaEvent_t evFork, evJoin, evMemH1;
    cudaEventCreateWithFlags(&evFork, cudaEventDisableTiming);
    cudaEventCreateWithFlags(&evJoin, cudaEventDisableTiming);
    cudaEventCreateWithFlags(&evMemH1, cudaEventDisableTiming);

    cudaEventRecord(evFork, 0);
    cudaStreamWaitEvent(s2, evFork, 0);

    // side branch: zero h1, then CSR build
    void* p = nullptr;
    cudaGetSymbolAddress(&p, g_h1);
    cudaMemsetAsync(p, 0, (size_t)Nn * 128 * sizeof(float), s2);
    cudaEventRecord(evMemH1, s2);
    void* pc = nullptr;
    cudaGetSymbolAddress(&pc, g_cnt);
    cudaMemsetAsync(pc, 0, (size_t)Nn * sizeof(int), s2);
    k_hist<<<(E + 255) / 256, 256, 0, s2>>>(ei, E);
    k_scan_part<<<nblk, 256, 0, s2>>>(Nn);
    k_scan_top<<<1, 256, 0, s2>>>(nblk);
    k_scan_final<<<nblk, 256, 0, s2>>>(Nn);
    k_fill<<<(E + 255) / 256, 256, 0, s2>>>(ei, E);
    cudaEventRecord(evJoin, s2);

    // main chain
    k_w1b<<<((KPAD / 2) * 128 + 255) / 256, 256>>>(W1);
    cudaStreamWaitEvent(0, evMemH1, 0);
    {
        dim3 grid((Nn + 127) / 128, KSPLIT);
        k_gemm1_mma<<<grid, 256, SMEM>>>(x, Nn);
    }
    k_h1bf<<<(Nn * 64 + 255) / 256, 256>>>(Nn);

    cudaStreamWaitEvent(0, evJoin, 0);

    { long long t = (long long)Nn * 32;
      k_gather1<<<(unsigned)((t + 255) / 256), 256>>>(b1, Nn); }

    k_gemm2<<<(Nn + 15) / 16, 256>>>(W2, Nn);
    { long long t = (long long)Nn * 16;
      k_gather2<<<(unsigned)((t + 255) / 256), 256>>>(b2, Nn); }

    { long long t = (long long)NL * 16;
      k_decode<<<(unsigned)((t + 255) / 256), 256>>>(eli, out, NL); }
}

// round 17
// speedup vs baseline: 1.1087x; 1.0255x over previous
#include <cuda_runtime.h>
#include <cuda_bf16.h>
#include <cstdint>

#define MAX_NODES 50000
#define MAX_EDGES 1600000
#define KDIM 3703
#define KPAD 3712
#define BK32 32
#define KSPLIT 3
// per-stage SMEM: A 128x36 fp32 (18432 B) + B 16x132 u32 (8448 B)
#define A_BYTES 18432
#define STAGE_BYTES 26880

__device__ float g_h1[MAX_NODES * 128];
__device__ uint32_t g_h1bf[MAX_NODES * 64];   // h1 * dinv[row], packed bf16x2
__device__ float g_agg1[MAX_NODES * 128];
__device__ uint32_t g_h2bf[MAX_NODES * 32];   // h2 * dinv[row], packed bf16x2
__device__ float g_z2[MAX_NODES * 64];
__device__ float g_dinv[MAX_NODES];
__device__ uint32_t g_W1B[(KPAD / 2) * 128];  // W1 as bf16x2 k-pairs
__device__ float g_zeros[16];
__device__ int g_cnt[MAX_NODES];
__device__ int g_row[MAX_NODES];
__device__ int g_cursor[MAX_NODES];
__device__ int g_part[256];
__device__ int g_partscan[256];
__device__ int g_csr_src[MAX_EDGES];

// ---------------- helpers ---------------------------------------------------------
__device__ __forceinline__ void cp4(uint32_t dst, const void* src) {
    asm volatile("cp.async.ca.shared.global [%0], [%1], 4;"
                 :: "r"(dst), "l"(src) : "memory");
}
__device__ __forceinline__ void cp16(uint32_t dst, const void* src) {
    asm volatile("cp.async.cg.shared.global [%0], [%1], 16;"
                 :: "r"(dst), "l"(src) : "memory");
}
#define CP_COMMIT() asm volatile("cp.async.commit_group;" ::: "memory")
#define CP_WAIT(n)  asm volatile("cp.async.wait_group %0;" :: "n"(n) : "memory")
__device__ __forceinline__ uint32_t smem_u32(const void* p) {
    uint32_t a;
    asm("{ .reg .u64 t; cvta.to.shared.u64 t, %1; cvt.u32.u64 %0, t; }"
        : "=r"(a) : "l"(p));
    return a;
}
__device__ __forceinline__ uint32_t pack_bf2(float lo, float hi) {
    uint32_t r;
    asm("cvt.rn.bf16x2.f32 %0, %1, %2;" : "=r"(r) : "f"(hi), "f"(lo));
    return r;
}
__device__ __forceinline__ float2 unpack_bf2(uint32_t u) {
    __nv_bfloat162 b = *reinterpret_cast<__nv_bfloat162*>(&u);
    return __bfloat1622float2(b);
}

// ---------------- W1 -> bf16x2 k-pairs [k/2][n], zero padded -----------------------
__global__ void k_w1b(const float* __restrict__ W1) {
    int idx = blockIdx.x * blockDim.x + threadIdx.x;
    if (idx >= (KPAD / 2) * 128) return;
    int kp = idx >> 7, n = idx & 127;
    int k = kp * 2;
    float lo = (k < KDIM)     ? W1[(long long)k * 128 + n]       : 0.0f;
    float hi = (k + 1 < KDIM) ? W1[(long long)(k + 1) * 128 + n] : 0.0f;
    g_W1B[idx] = pack_bf2(lo, hi);
}

// ---------------- CSR build ---------------------------------------------------------
__global__ void k_hist(const int* __restrict__ ei, int E) {
    int e = blockIdx.x * blockDim.x + threadIdx.x;
    if (e < E) atomicAdd(&g_cnt[ei[E + e]], 1);
}
__global__ void k_scan_part(int n) {
    __shared__ int sh[256];
    int i = blockIdx.x * 256 + threadIdx.x;
    int v = (i < n) ? g_cnt[i] : 0;
    sh[threadIdx.x] = v;
    __syncthreads();
    for (int off = 128; off > 0; off >>= 1) {
        if (threadIdx.x < off) sh[threadIdx.x] += sh[threadIdx.x + off];
        __syncthreads();
    }
    if (threadIdx.x == 0) g_part[blockIdx.x] = sh[0];
}
__global__ void k_scan_top(int nblk) {
    __shared__ int sh[256];
    int tid = threadIdx.x;
    int v = (tid < nblk) ? g_part[tid] : 0;
    sh[tid] = v;
    __syncthreads();
    for (int off = 1; off < 256; off <<= 1) {
        int t = (tid >= off) ? sh[tid - off] : 0;
        __syncthreads();
        sh[tid] += t;
        __syncthreads();
    }
    g_partscan[tid] = sh[tid] - v;
}
__global__ void k_scan_final(int n) {
    __shared__ int sh[256];
    int i = blockIdx.x * 256 + threadIdx.x;
    int tid = threadIdx.x;
    int v = (i < n) ? g_cnt[i] : 0;
    sh[tid] = v;
    __syncthreads();
    for (int off = 1; off < 256; off <<= 1) {
        int t = (tid >= off) ? sh[tid - off] : 0;
        __syncthreads();
        sh[tid] += t;
        __syncthreads();
    }
    if (i < n) {
        int rs = sh[tid] - v + g_partscan[blockIdx.x];
        g_row[i] = rs;
        g_cursor[i] = rs;
        g_dinv[i] = rsqrtf((float)(v + 1));
    }
}
__global__ void k_fill(const int* __restrict__ ei, int E) {
    int e = blockIdx.x * blockDim.x + threadIdx.x;
    if (e >= E) return;
    int s = ei[e], d = ei[E + e];
    int slot = atomicAdd(&g_cursor[d], 1);
    g_csr_src[slot] = s;
}

// ---------------- GEMM1 split-K=3 (39/39/38 x BK32) bf16 m16n8k16 -------------------
// A SMEM row = 36 fp32 (aligned 144B superset of the 32-float window); per-row
// skew off = ((mg*3 + k0) & 3). Garbage at k>=KDIM cancelled by zero-padded B.
__global__ __launch_bounds__(256, 2)
void k_gemm1_mma(const float* __restrict__ A, int M) {
    extern __shared__ char dyn[];
    const int tid = threadIdx.x;
    const int wid = tid >> 5;
    const int lane = tid & 31;
    const int grp = lane >> 2, tg = lane & 3;
    const int warp_m = wid >> 2, warp_n = wid & 3;   // 2x4 warps: 64-row x 32-col
    const int m0 = blockIdx.x * 128;
    const int y = blockIdx.y;
    const int kb_ch = (y == 0) ? 0 : (y == 1 ? 39 : 78);
    const int nsteps = (y == 2) ? 38 : 39;

    const uint32_t smem0 = smem_u32(dyn);

    float acc[4][4][4];
#pragma unroll
    for (int i = 0; i < 4; i++)
#pragma unroll
        for (int j = 0; j < 4; j++)
#pragma unroll
            for (int v = 0; v < 4; v++) acc[i][j][v] = 0.0f;

    auto load_stage = [&](int c, int s) {
        const int k0 = (kb_ch + c) * BK32;
        const uint32_t sA = smem0 + s * STAGE_BYTES;
        const uint32_t sB = sA + A_BYTES;
        if (k0 + 36 <= KDIM) {
#pragma unroll
            for (int i = 0; i < 5; i++) {
                int idx = i * 256 + tid;
                if (idx < 1152) {
                    int row = idx / 9, part = idx - row * 9;
                    int mg = m0 + row;
                    const float* src;
                    if (mg < M) {
                        long long g = (long long)mg * KDIM + k0;
                        src = A + (g & ~3LL) + part * 4;
                    } else {
                        src = g_zeros;
                    }
                    cp16(sA + (uint32_t)((row * 36 + part * 4) * 4), src);
                }
            }
        } else {
#pragma unroll
            for (int i = 0; i < 16; i++) {
                int idx = i * 256 + tid;
                int row = idx >> 5, kk = idx & 31;
                int mg = m0 + row, k = k0 + kk;
                int off = (mg * 3 + k0) & 3;
                const float* src = (mg < M && k < KDIM)
                                 ? A + (long long)mg * KDIM + k : g_zeros;
                cp4(sA + (uint32_t)((row * 36 + off + kk) * 4), src);
            }
        }
#pragma unroll
        for (int i = 0; i < 2; i++) {
            int idx = i * 256 + tid;
            int kp = idx >> 5, n4 = (idx & 31) * 4;
            cp16(sB + (uint32_t)((kp * 132 + n4) * 4),
                 g_W1B + (long long)(k0 / 2 + kp) * 128 + n4);
        }
        CP_COMMIT();
    };

    load_stage(0, 0);
    for (int c = 0; c < nsteps; c++) {
        const int s = c & 1;
        if (c + 1 < nsteps) { load_stage(c + 1, s ^ 1); CP_WAIT(1); }
        else                { CP_WAIT(0); }
        __syncthreads();
        const int k0 = (kb_ch + c) * BK32;
        const float*    Asb = (const float*)(dyn + s * STAGE_BYTES);
        const uint32_t* Bsb = (const uint32_t*)(dyn + s * STAGE_BYTES + A_BYTES);

#pragma unroll
        for (int half = 0; half < 2; half++) {
            const int kk = half * 16;
            uint32_t bf[4][2];
#pragma unroll
            for (int nt = 0; nt < 4; nt++) {
                int n = warp_n * 32 + nt * 8 + grp;
                bf[nt][0] = Bsb[(half * 8 + tg) * 132 + n];
                bf[nt][1] = Bsb[(half * 8 + tg + 4) * 132 + n];
            }
#pragma unroll
            for (int mt = 0; mt < 4; mt++) {
                int r = warp_m * 64 + mt * 16 + grp;
                int r2 = r + 8;
                int off1 = ((m0 + r) * 3 + k0) & 3;
                int off2 = ((m0 + r2) * 3 + k0) & 3;
                const float* A1 = Asb + r * 36 + off1 + kk;
                const float* A2 = Asb + r2 * 36 + off2 + kk;
                uint32_t a0 = pack_bf2(A1[2 * tg],     A1[2 * tg + 1]);
                uint32_t a1 = pack_bf2(A2[2 * tg],     A2[2 * tg + 1]);
                uint32_t a2 = pack_bf2(A1[2 * tg + 8], A1[2 * tg + 9]);
                uint32_t a3 = pack_bf2(A2[2 * tg + 8], A2[2 * tg + 9]);
#pragma unroll
                for (int nt = 0; nt < 4; nt++) {
                    asm volatile(
                        "mma.sync.aligned.m16n8k16.row.col.f32.bf16.bf16.f32 "
                        "{%0, %1, %2, %3}, {%4, %5, %6, %7}, {%8, %9}, "
                        "{%0, %1, %2, %3};"
                        : "+f"(acc[mt][nt][0]), "+f"(acc[mt][nt][1]),
                          "+f"(acc[mt][nt][2]), "+f"(acc[mt][nt][3])
                        : "r"(a0), "r"(a1), "r"(a2), "r"(a3),
                          "r"(bf[nt][0]), "r"(bf[nt][1]));
                }
            }
        }
        __syncthreads();
    }
#pragma unroll
    for (int mt = 0; mt < 4; mt++) {
        int r = m0 + warp_m * 64 + mt * 16 + grp;
#pragma unroll
        for (int nt = 0; nt < 4; nt++) {
            int col = warp_n * 32 + nt * 8 + tg * 2;
            if (r < M) {
                float* p = g_h1 + (long long)r * 128 + col;
                asm volatile("red.global.add.v2.f32 [%0], {%1, %2};"
                             :: "l"(p), "f"(acc[mt][nt][0]), "f"(acc[mt][nt][1])
                             : "memory");
            }
            if (r + 8 < M) {
                float* p = g_h1 + (long long)(r + 8) * 128 + col;
                asm volatile("red.global.add.v2.f32 [%0], {%1, %2};"
                             :: "l"(p), "f"(acc[mt][nt][2]), "f"(acc[mt][nt][3])
                             : "memory");
            }
        }
    }
}

// ---------------- h1 -> packed bf16, pre-scaled by dinv[row] ------------------------
__global__ void k_h1bf(int n) {
    int i = blockIdx.x * blockDim.x + threadIdx.x;
    if (i >= n * 64) return;
    float di = g_dinv[i >> 6];
    float2 v = ((const float2*)g_h1)[i];
    g_h1bf[i] = pack_bf2(v.x * di, v.y * di);
}

// ---------------- layer-1 gather (warp per node; pre-scaled rows; pure sum) ---------
__global__ void k_gather1(const float* __restrict__ b1, int n) {
    long long gid = (long long)blockIdx.x * blockDim.x + threadIdx.x;
    int i = (int)(gid >> 5);
    if (i >= n) return;
    int l = (int)gid & 31;
    float di = g_dinv[i];
    // self term: row already scaled by dinv[i]
    uint2 us = *(const uint2*)(g_h1bf + (long long)i * 64 + l * 2);
    float2 sa = unpack_bf2(us.x), sb = unpack_bf2(us.y);
    float4 acc = make_float4(sa.x, sa.y, sb.x, sb.y);
    int rs = g_row[i], re = rs + g_cnt[i];
    int j = rs;
    for (; j + 8 <= re; j += 8) {
        uint2 u[8];
#pragma unroll
        for (int q = 0; q < 8; q++)
            u[q] = *(const uint2*)(g_h1bf + (long long)g_csr_src[j + q] * 64 + l * 2);
#pragma unroll
        for (int q = 0; q < 8; q++) {
            float2 a = unpack_bf2(u[q].x), b = unpack_bf2(u[q].y);
            acc.x += a.x; acc.y += a.y;
            acc.z += b.x; acc.w += b.y;
        }
    }
    for (; j < re; j++) {
        uint2 u = *(const uint2*)(g_h1bf + (long long)g_csr_src[j] * 64 + l * 2);
        float2 a = unpack_bf2(u.x), b = unpack_bf2(u.y);
        acc.x += a.x; acc.y += a.y;
        acc.z += b.x; acc.w += b.y;
    }
    float4 bb = *(const float4*)(b1 + l * 4);
    *(float4*)(g_agg1 + (long long)i * 128 + l * 4) =
        make_float4(acc.x * di + bb.x, acc.y * di + bb.y,
                    acc.z * di + bb.z, acc.w * di + bb.w);
}

// ---------------- GEMM2 (writes h2 * dinv[node] as packed bf16) ---------------------
__global__ __launch_bounds__(256)
void k_gemm2(const float* __restrict__ W2, int M) {
    __shared__ float Ws[128 * 64];
    __shared__ float Zs[16 * 128];
    const int tid = threadIdx.x;
    const int n0 = blockIdx.x * 16;
#pragma unroll
    for (int i = 0; i < 8; i++)
        ((float4*)Ws)[i * 256 + tid] = ((const float4*)W2)[i * 256 + tid];
#pragma unroll
    for (int i = 0; i < 2; i++) {
        int f4 = i * 256 + tid;
        int node = n0 + (f4 >> 5);
        float4 v = make_float4(0.f, 0.f, 0.f, 0.f);
        if (node < M) v = ((const float4*)(g_agg1 + (long long)node * 128))[f4 & 31];
        v.x = fmaxf(v.x, 0.f); v.y = fmaxf(v.y, 0.f);
        v.z = fmaxf(v.z, 0.f); v.w = fmaxf(v.w, 0.f);
        ((float4*)Zs)[f4] = v;
    }
    __syncthreads();
    const int ny = tid / 16, nx = (tid % 16) * 4;
    float4 acc = make_float4(0.f, 0.f, 0.f, 0.f);
#pragma unroll
    for (int k = 0; k < 128; k++) {
        float a = Zs[ny * 128 + k];
        float4 w = *(const float4*)(&Ws[k * 64 + nx]);
        acc.x += a * w.x; acc.y += a * w.y;
        acc.z += a * w.z; acc.w += a * w.w;
    }
    int node = n0 + ny;
    if (node < M) {
        float di = g_dinv[node];
        uint2 packed = make_uint2(pack_bf2(acc.x * di, acc.y * di),
                                  pack_bf2(acc.z * di, acc.w * di));
        *(uint2*)(g_h2bf + (long long)node * 32 + nx / 2) = packed;
    }
}

// ---------------- layer-2 gather (16 lanes per node; pre-scaled rows) ----------------
__global__ void k_gather2(const float* __restrict__ b2, int n) {
    long long gid = (long long)blockIdx.x * blockDim.x + threadIdx.x;
    int i = (int)(gid >> 4);
    if (i >= n) return;
    int l = (int)gid & 15;
    float di = g_dinv[i];
    uint2 us = *(const uint2*)(g_h2bf + (long long)i * 32 + l * 2);
    float2 sa = unpack_bf2(us.x), sb = unpack_bf2(us.y);
    float4 acc = make_float4(sa.x, sa.y, sb.x, sb.y);
    int rs = g_row[i], re = rs + g_cnt[i];
    int j = rs;
    for (; j + 8 <= re; j += 8) {
        uint2 u[8];
#pragma unroll
        for (int q = 0; q < 8; q++)
            u[q] = *(const uint2*)(g_h2bf + (long long)g_csr_src[j + q] * 32 + l * 2);
#pragma unroll
        for (int q = 0; q < 8; q++) {
            float2 a = unpack_bf2(u[q].x), b = unpack_bf2(u[q].y);
            acc.x += a.x; acc.y += a.y;
            acc.z += b.x; acc.w += b.y;
        }
    }
    for (; j < re; j++) {
        uint2 u = *(const uint2*)(g_h2bf + (long long)g_csr_src[j] * 32 + l * 2);
        float2 a = unpack_bf2(u.x), b = unpack_bf2(u.y);
        acc.x += a.x; acc.y += a.y;
        acc.z += b.x; acc.w += b.y;
    }
    float4 bb = *(const float4*)(b2 + l * 4);
    *(float4*)(g_z2 + (long long)i * 64 + l * 4) =
        make_float4(acc.x * di + bb.x, acc.y * di + bb.y,
                    acc.z * di + bb.z, acc.w * di + bb.w);
}

// ---------------- decoder (16 lanes per edge, float4) ----------------------------------
__global__ void k_decode(const int* __restrict__ eli, float* __restrict__ out,
                         int NL) {
    long long gid = (long long)blockIdx.x * blockDim.x + threadIdx.x;
    int e = (int)(gid >> 4);
    if (e >= NL) return;
    int l = (int)gid & 15;
    int a = eli[e], b = eli[NL + e];
    float4 va = *(const float4*)(g_z2 + (long long)a * 64 + l * 4);
    float4 vb = *(const float4*)(g_z2 + (long long)b * 64 + l * 4);
    float p = va.x * vb.x + va.y * vb.y + va.z * vb.z + va.w * vb.w;
#pragma unroll
    for (int off = 8; off > 0; off >>= 1)
        p += __shfl_xor_sync(0xFFFFFFFFu, p, off);
    if (l == 0) out[e] = p;
}

// ---------------- launch ---------------------------------------------------------------------
extern "C" void kernel_launch(void* const* d_in, const int* in_sizes, int n_in,
                              void* d_out, int out_size) {
    const float* x  = (const float*)d_in[0];
    const float* W1 = (const float*)d_in[1];
    const float* b1 = (const float*)d_in[2];
    const float* W2 = (const float*)d_in[3];
    const float* b2 = (const float*)d_in[4];
    const int* ei  = (const int*)d_in[5];
    const int* eli = (const int*)d_in[6];
    float* out = (float*)d_out;

    const int K  = in_sizes[1] / 128;
    const int Nn = in_sizes[0] / K;
    const int E  = in_sizes[5] / 2;
    const int NL = in_sizes[6] / 2;
    const int nblk = (Nn + 255) / 256;
    const int SMEM = 2 * STAGE_BYTES;   // 53760 B

    cudaFuncSetAttribute(k_gemm1_mma, cudaFuncAttributeMaxDynamicSharedMemorySize,
                         SMEM);

    // side stream + fork/join events
    cudaStream_t s2;
    cudaStreamCreateWithFlags(&s2, cudaStreamNonBlocking);
    cudaEvent_t evFork, evJoin, evMemH1;
    cudaEventCreateWithFlags(&evFork, cudaEventDisableTiming);
    cudaEventCreateWithFlags(&evJoin, cudaEventDisableTiming);
    cudaEventCreateWithFlags(&evMemH1, cudaEventDisableTiming);

    cudaEventRecord(evFork, 0);
    cudaStreamWaitEvent(s2, evFork, 0);

    // side branch: zero h1, then CSR build
    void* p = nullptr;
    cudaGetSymbolAddress(&p, g_h1);
    cudaMemsetAsync(p, 0, (size_t)Nn * 128 * sizeof(float), s2);
    cudaEventRecord(evMemH1, s2);
    void* pc = nullptr;
    cudaGetSymbolAddress(&pc, g_cnt);
    cudaMemsetAsync(pc, 0, (size_t)Nn * sizeof(int), s2);
    k_hist<<<(E + 255) / 256, 256, 0, s2>>>(ei, E);
    k_scan_part<<<nblk, 256, 0, s2>>>(Nn);
    k_scan_top<<<1, 256, 0, s2>>>(nblk);
    k_scan_final<<<nblk, 256, 0, s2>>>(Nn);
    k_fill<<<(E + 255) / 256, 256, 0, s2>>>(ei, E);
    cudaEventRecord(evJoin, s2);

    // main chain
    k_w1b<<<((KPAD / 2) * 128 + 255) / 256, 256>>>(W1);
    cudaStreamWaitEvent(0, evMemH1, 0);
    {
        dim3 grid((Nn + 127) / 128, KSPLIT);
        k_gemm1_mma<<<grid, 256, SMEM>>>(x, Nn);
    }

    // h1bf needs dinv (from CSR branch) and h1 (from gemm1)
    cudaStreamWaitEvent(0, evJoin, 0);
    k_h1bf<<<(Nn * 64 + 255) / 256, 256>>>(Nn);

    { long long t = (long long)Nn * 32;
      k_gather1<<<(unsigned)((t + 255) / 256), 256>>>(b1, Nn); }

    k_gemm2<<<(Nn + 15) / 16, 256>>>(W2, Nn);
    { long long t = (long long)Nn * 16;
      k_gather2<<<(unsigned)((t + 255) / 256), 256>>>(b2, Nn); }

    { long long t = (long long)NL * 16;
      k_decode<<<(unsigned)((t + 255) / 256), 256>>>(eli, out, NL); }
}